// round 16
// baseline (speedup 1.0000x reference)
#include <cuda_runtime.h>
#include <cuda_fp16.h>

#define TT 512
#define BB 512
#define DD 16
#define HH 64
#define XT 64          // timesteps per staged x block in xg kernel
#define NXB (TT / XT)
#define XBB (XT * DD * 4)     // bytes of x per block = 4096
#define BK 16          // timesteps per staged xg block in rec kernel
#define NBK (TT / BK)
#define XGBB (BK * 256 * 2)   // bytes per staged block = 8192

typedef unsigned long long ull;

__device__ __forceinline__ ull fma2(ull a, ull b, ull c) {
    ull d;
    asm("fma.rn.f32x2 %0, %1, %2, %3;" : "=l"(d) : "l"(a), "l"(b), "l"(c));
    return d;
}
__device__ __forceinline__ float hadd2(ull a) {
    return __uint_as_float((unsigned)a) + __uint_as_float((unsigned)(a >> 32));
}
__device__ __forceinline__ float tanha(float x) {
    float y;
    asm("tanh.approx.f32 %0, %1;" : "=f"(y) : "f"(x));
    return y;
}
__device__ __forceinline__ float siga(float x) {
    return fmaf(0.5f, tanha(0.5f * x), 0.5f);
}
__device__ __forceinline__ void cpa16(unsigned smem, const void* gmem) {
    asm volatile("cp.async.ca.shared.global [%0], [%1], 16;\n"
                 :: "r"(smem), "l"(gmem));
}
__device__ __forceinline__ void cpa_commit() {
    asm volatile("cp.async.commit_group;\n" ::: "memory");
}
__device__ __forceinline__ void cpa_wait1() {
    asm volatile("cp.async.wait_group 1;\n" ::: "memory");
}

// scratch: xg[b][t][u][{r,z,n,pad}] fp16; r,z include b_ih+b_hh, n includes b_ih
__device__ __half g_xg[(size_t)BB * TT * 256];

// ---------------------------------------------------------------------------
// Kernel 1: xg precompute (persistent-row, R15). Grid 512 = single wave.
// ---------------------------------------------------------------------------
__global__ __launch_bounds__(128, 4)
void xg_kernel(const float* __restrict__ x,
               const float* __restrict__ w_ih,
               const float* __restrict__ b_ih,
               const float* __restrict__ b_hh)
{
    __shared__ __align__(16) float xs[2][XT * DD];   // 2 x 4KB
    const int tid = threadIdx.x;
    const int u   = tid & 63;
    const int th  = tid >> 6;
    const int b   = blockIdx.x;

    ulonglong2 wv[3][DD / 4];
    {
        const int rows[3] = { u, HH + u, 2 * HH + u };
        #pragma unroll
        for (int g = 0; g < 3; g++) {
            const ulonglong2* p = (const ulonglong2*)(w_ih + rows[g] * DD);
            #pragma unroll
            for (int j = 0; j < DD / 4; j++) wv[g][j] = p[j];
        }
    }
    const float br = b_ih[u]          + b_hh[u];
    const float bz = b_ih[HH + u]     + b_hh[HH + u];
    const float bn = b_ih[2 * HH + u];

    const char* xg_row = (const char*)(x + (size_t)b * TT * DD);
    const unsigned xs_sb = (unsigned)__cvta_generic_to_shared(&xs[0][0]);

    #pragma unroll
    for (int c = 0; c < 2; c++)
        cpa16(xs_sb + (tid + 128 * c) * 16, xg_row + (tid + 128 * c) * 16);
    cpa_commit();
    __syncthreads();

    for (int blk = 0; blk < NXB; ++blk) {
        if (blk + 1 < NXB) {
            unsigned dst = xs_sb + ((blk & 1) ? 0u : (unsigned)XBB);
            const char* src = xg_row + (size_t)(blk + 1) * XBB;
            #pragma unroll
            for (int c = 0; c < 2; c++)
                cpa16(dst + (tid + 128 * c) * 16, src + (tid + 128 * c) * 16);
        }
        cpa_commit();
        cpa_wait1();
        __syncthreads();

        const float* xbuf = &xs[blk & 1][0];
        __half* outp = g_xg + ((size_t)(b * TT + blk * XT + th * (XT / 2)) * 256) + u * 4;

        #pragma unroll 4
        for (int k = 0; k < XT / 2; k++) {
            const int tt = th * (XT / 2) + k;
            const ulonglong2* xp = (const ulonglong2*)(xbuf + tt * DD);
            ull a0 = 0ull, a1 = 0ull, a2 = 0ull;
            #pragma unroll
            for (int j = 0; j < DD / 4; j++) {
                ulonglong2 xv = xp[j];
                a0 = fma2(wv[0][j].x, xv.x, a0);
                a0 = fma2(wv[0][j].y, xv.y, a0);
                a1 = fma2(wv[1][j].x, xv.x, a1);
                a1 = fma2(wv[1][j].y, xv.y, a1);
                a2 = fma2(wv[2][j].x, xv.x, a2);
                a2 = fma2(wv[2][j].y, xv.y, a2);
            }
            __half2 rz = __floats2half2_rn(hadd2(a0) + br, hadd2(a1) + bz);
            __half2 n0 = __floats2half2_rn(hadd2(a2) + bn, 0.f);
            uint2 pkt;
            pkt.x = *reinterpret_cast<unsigned*>(&rz);
            pkt.y = *reinterpret_cast<unsigned*>(&n0);
            *reinterpret_cast<uint2*>(outp + (size_t)k * 256) = pkt;
        }
        __syncthreads();
    }
}

// ---------------------------------------------------------------------------
// Kernel 2: forward recurrence, intra-warp k-split (R14) with REGISTER DIET
// so 4 CTAs/SM are guaranteed (regs target <=124 -> 512 CTAs in ONE wave,
// 3.46 warps/SMSP on all 4 SMSPs). Warp w: units [16w,16w+16); lane l:
// u = 16w+(l&15), k-half kh = l>>4. 96 weight regs; 3 single accumulation
// chains (latency hidden by co-resident warps); shfl.bfly(16) exchange;
// redundant finalize; ONE __syncthreads per step.
// ---------------------------------------------------------------------------
__global__ __launch_bounds__(128, 4)
void gru_rec_kernel(const float* __restrict__ w_hh,
                    const float* __restrict__ b_hh,
                    const float* __restrict__ x,
                    const float* __restrict__ w_ih_b,
                    const float* __restrict__ b_ih_b,
                    const float* __restrict__ b_hh_b,
                    const float* __restrict__ fc_w,
                    const float* __restrict__ fc_b,
                    float* __restrict__ out)
{
    __shared__ __align__(16) float h_sh[2][HH];
    __shared__ __align__(16) __half xg_sh[2][BK * 256];   // 2 x 8KB
    __shared__ float red_sh[HH];

    const int tid  = threadIdx.x;
    const int lane = tid & 31;
    const int u    = 16 * (tid >> 5) + (lane & 15);
    const int kh   = lane >> 4;
    const int b    = blockIdx.x;

    // half-rows r(u), z(u), n(u) of w_hh over k in [32kh, 32kh+32): 96 regs
    ulonglong2 w0[8], w1[8], w2[8];
    {
        const ulonglong2* p0 = (const ulonglong2*)(w_hh + u * HH + 32 * kh);
        const ulonglong2* p1 = (const ulonglong2*)(w_hh + (HH + u) * HH + 32 * kh);
        const ulonglong2* p2 = (const ulonglong2*)(w_hh + (2 * HH + u) * HH + 32 * kh);
        #pragma unroll
        for (int j = 0; j < 8; j++) { w0[j] = p0[j]; w1[j] = p1[j]; w2[j] = p2[j]; }
    }
    const float bhn = b_hh[2 * HH + u];

    const char* xg_g = (const char*)(g_xg + (size_t)b * TT * 256) + tid * 16;
    const unsigned xg_sb = (unsigned)__cvta_generic_to_shared(&xg_sh[0][0]) + tid * 16;

    float hold = 0.f;
    if (lane < 16) h_sh[0][u] = 0.f;

    // prologue: stage block 0 into buffer 0 (4 chunks of 16B per thread)
    #pragma unroll
    for (int c = 0; c < 4; c++)
        cpa16(xg_sb + 2048 * c, xg_g + 2048 * c);
    cpa_commit();
    __syncthreads();

    int p = 0;
    for (int blk = 0; blk < NBK; ++blk) {
        if (blk + 1 < NBK) {
            unsigned dst = xg_sb + ((blk & 1) ? 0u : (unsigned)XGBB);
            const char* src = xg_g + (size_t)(blk + 1) * XGBB;
            #pragma unroll
            for (int c = 0; c < 4; c++)
                cpa16(dst + 2048 * c, src + 2048 * c);
        }
        cpa_commit();
        cpa_wait1();
        __syncthreads();

        const __half* xb = &xg_sh[blk & 1][0];

        #pragma unroll 4
        for (int tt = 0; tt < BK; ++tt) {
            uint2 pkt = *reinterpret_cast<const uint2*>(xb + tt * 256 + u * 4);

            const ulonglong2* hp = (const ulonglong2*)&h_sh[p][32 * kh];
            ull a0 = 0ull, a1 = 0ull, a2 = 0ull;
            #pragma unroll
            for (int j = 0; j < 8; j++) {
                ulonglong2 hv = hp[j];
                a0 = fma2(w0[j].x, hv.x, a0); a0 = fma2(w0[j].y, hv.y, a0);
                a1 = fma2(w1[j].x, hv.x, a1); a1 = fma2(w1[j].y, hv.y, a1);
                a2 = fma2(w2[j].x, hv.x, a2); a2 = fma2(w2[j].y, hv.y, a2);
            }
            float p0 = hadd2(a0);
            float p1 = hadd2(a1);
            float p2 = hadd2(a2);

            // partner lane (l ^ 16) holds the other k-half
            float q0 = __shfl_xor_sync(0xffffffffu, p0, 16);
            float q1 = __shfl_xor_sync(0xffffffffu, p1, 16);
            float q2 = __shfl_xor_sync(0xffffffffu, p2, 16);

            float2 rzx = __half22float2(*reinterpret_cast<__half2*>(&pkt.x));
            float  xn  = __half2float(*reinterpret_cast<__half*>(&pkt.y));

            // redundant finalize (commutative adds -> both halves identical)
            float rr = siga(rzx.x + (p0 + q0));
            float zz = siga(rzx.y + (p1 + q1));
            float nn = tanha(fmaf(rr, (p2 + q2) + bhn, xn));
            hold = fmaf(zz, hold - nn, nn);     // (1-z)n + z h

            if (lane < 16) h_sh[p ^ 1][u] = hold;
            __syncthreads();
            p ^= 1;
        }
    }

    // ---- epilogue: backward GRU = ONE step from h=0 on x[:,T-1,:]; then fc ----
    if (tid < HH) {
        const int j = tid;
        const float* xl = x + ((size_t)b * TT + (TT - 1)) * DD;

        float ar  = __ldg(b_ih_b + j)          + __ldg(b_hh_b + j);
        float az  = __ldg(b_ih_b + HH + j)     + __ldg(b_hh_b + HH + j);
        float anx = __ldg(b_ih_b + 2 * HH + j);
        float anh = __ldg(b_hh_b + 2 * HH + j);
        const float* wr = w_ih_b + (size_t)j * DD;
        const float* wz = w_ih_b + (size_t)(HH + j) * DD;
        const float* wn = w_ih_b + (size_t)(2 * HH + j) * DD;
        #pragma unroll
        for (int k = 0; k < DD; k++) {
            float xv = __ldg(xl + k);
            ar  += __ldg(wr + k) * xv;
            az  += __ldg(wz + k) * xv;
            anx += __ldg(wn + k) * xv;
        }
        float rb = siga(ar);
        float zb = siga(az);
        float nb = tanha(anx + rb * anh);
        float hb = (1.f - zb) * nb;            // h_prev = 0

        red_sh[j] = h_sh[p][j] * __ldg(fc_w + j) + hb * __ldg(fc_w + HH + j);
    }
    __syncthreads();
    if (tid == 0) {
        float sum = __ldg(fc_b);
        #pragma unroll
        for (int k = 0; k < HH; k++) sum += red_sh[k];
        out[b] = sum;
    }
}

extern "C" void kernel_launch(void* const* d_in, const int* in_sizes, int n_in,
                              void* d_out, int out_size)
{
    const float* x      = (const float*)d_in[0];
    const float* w_ih_f = (const float*)d_in[1];
    const float* w_hh_f = (const float*)d_in[2];
    const float* b_ih_f = (const float*)d_in[3];
    const float* b_hh_f = (const float*)d_in[4];
    const float* w_ih_b = (const float*)d_in[5];
    /* d_in[6] = w_hh_b unused: backward direction starts from h=0 */
    const float* b_ih_b = (const float*)d_in[7];
    const float* b_hh_b = (const float*)d_in[8];
    const float* fc_w   = (const float*)d_in[9];
    const float* fc_b   = (const float*)d_in[10];

    xg_kernel<<<BB, 128>>>(x, w_ih_f, b_ih_f, b_hh_f);
    gru_rec_kernel<<<BB, 128>>>(w_hh_f, b_hh_f, x,
                                w_ih_b, b_ih_b, b_hh_b,
                                fc_w, fc_b, (float*)d_out);
}

// round 17
// speedup vs baseline: 1.1583x; 1.1583x over previous
#include <cuda_runtime.h>
#include <cuda_fp16.h>

#define TT 512
#define BB 512
#define DD 16
#define HH 64
#define XT 64                 // timesteps per staged x block in xg kernel
#define XHALF 256             // timesteps per xg CTA (half row)
#define NXB (XHALF / XT)      // 4 blocks per xg CTA
#define XBB (XT * DD * 4)     // bytes of x per block = 4096
#define BK 32                 // timesteps per staged xg block in rec kernel
#define NBK (TT / BK)
#define XGBB (BK * 256 * 2)   // bytes per staged block = 16384

typedef unsigned long long ull;

__device__ __forceinline__ ull fma2(ull a, ull b, ull c) {
    ull d;
    asm("fma.rn.f32x2 %0, %1, %2, %3;" : "=l"(d) : "l"(a), "l"(b), "l"(c));
    return d;
}
__device__ __forceinline__ ull addf2(ull a, ull b) {
    ull d;
    asm("add.rn.f32x2 %0, %1, %2;" : "=l"(d) : "l"(a), "l"(b));
    return d;
}
__device__ __forceinline__ float hadd2(ull a) {
    return __uint_as_float((unsigned)a) + __uint_as_float((unsigned)(a >> 32));
}
__device__ __forceinline__ float tanha(float x) {
    float y;
    asm("tanh.approx.f32 %0, %1;" : "=f"(y) : "f"(x));
    return y;
}
__device__ __forceinline__ float siga(float x) {
    return fmaf(0.5f, tanha(0.5f * x), 0.5f);
}
__device__ __forceinline__ void cpa16(unsigned smem, const void* gmem) {
    asm volatile("cp.async.ca.shared.global [%0], [%1], 16;\n"
                 :: "r"(smem), "l"(gmem));
}
__device__ __forceinline__ void cpa_commit() {
    asm volatile("cp.async.commit_group;\n" ::: "memory");
}
__device__ __forceinline__ void cpa_wait1() {
    asm volatile("cp.async.wait_group 1;\n" ::: "memory");
}
__device__ __forceinline__ void cpa_wait2() {
    asm volatile("cp.async.wait_group 2;\n" ::: "memory");
}

// scratch: xg[b][t][u][{r,z,n,pad}] fp16; r,z include b_ih+b_hh, n includes b_ih
__device__ __half g_xg[(size_t)BB * TT * 256];

// ---------------------------------------------------------------------------
// Kernel 1: xg precompute v3. Grid 1024 = half-row per CTA (6.9 CTAs/SM,
// deep warp pool hides all latency; single wave). Triple-buffered cp.async
// (wait_group 2) -> ONE __syncthreads per 64-t block. 2-t inner unroll.
// thread = (unit u, t-half th); packed {r,z,n,0} STG.64 out.
// ---------------------------------------------------------------------------
__global__ __launch_bounds__(128)
void xg_kernel(const float* __restrict__ x,
               const float* __restrict__ w_ih,
               const float* __restrict__ b_ih,
               const float* __restrict__ b_hh)
{
    __shared__ __align__(16) float xs[3][XT * DD];   // 3 x 4KB
    const int tid  = threadIdx.x;
    const int u    = tid & 63;
    const int th   = tid >> 6;
    const int b    = blockIdx.x >> 1;
    const int t0   = (blockIdx.x & 1) * XHALF;

    ulonglong2 wv[3][DD / 4];
    {
        const int rows[3] = { u, HH + u, 2 * HH + u };
        #pragma unroll
        for (int g = 0; g < 3; g++) {
            const ulonglong2* p = (const ulonglong2*)(w_ih + rows[g] * DD);
            #pragma unroll
            for (int j = 0; j < DD / 4; j++) wv[g][j] = p[j];
        }
    }
    const float br = b_ih[u]          + b_hh[u];
    const float bz = b_ih[HH + u]     + b_hh[HH + u];
    const float bn = b_ih[2 * HH + u];

    const char* xrow = (const char*)(x + ((size_t)b * TT + t0) * DD);
    const unsigned xs_sb = (unsigned)__cvta_generic_to_shared(&xs[0][0]);

    // prologue: stage blocks 0 and 1 (2 chunks of 16B per thread per block)
    #pragma unroll
    for (int c = 0; c < 2; c++)
        cpa16(xs_sb + (tid + 128 * c) * 16, xrow + (tid + 128 * c) * 16);
    cpa_commit();
    #pragma unroll
    for (int c = 0; c < 2; c++)
        cpa16(xs_sb + XBB + (tid + 128 * c) * 16, xrow + XBB + (tid + 128 * c) * 16);
    cpa_commit();

    for (int blk = 0; blk < NXB; ++blk) {
        // issue blk+2 into buffer (blk+2)%3 (reuse safe: read at blk-1,
        // all threads past that block's barrier)
        if (blk + 2 < NXB) {
            unsigned dst = xs_sb + (unsigned)(((blk + 2) % 3) * XBB);
            const char* src = xrow + (size_t)(blk + 2) * XBB;
            #pragma unroll
            for (int c = 0; c < 2; c++)
                cpa16(dst + (tid + 128 * c) * 16, src + (tid + 128 * c) * 16);
        }
        cpa_commit();
        cpa_wait2();        // block blk landed (2 newer groups may be in flight)
        __syncthreads();    // ONE barrier per block

        const float* xbuf = &xs[blk % 3][0];
        __half* outp = g_xg + ((size_t)(b * TT + t0 + blk * XT + th * (XT / 2)) * 256) + u * 4;

        #pragma unroll 4
        for (int k = 0; k < XT / 2; k += 2) {
            const int tt = th * (XT / 2) + k;
            const ulonglong2* xp0 = (const ulonglong2*)(xbuf + tt * DD);
            const ulonglong2* xp1 = (const ulonglong2*)(xbuf + (tt + 1) * DD);
            ull a0 = 0ull, a1 = 0ull, a2 = 0ull;
            ull d0 = 0ull, d1 = 0ull, d2 = 0ull;
            #pragma unroll
            for (int j = 0; j < DD / 4; j++) {
                ulonglong2 xv0 = xp0[j];
                ulonglong2 xv1 = xp1[j];
                a0 = fma2(wv[0][j].x, xv0.x, a0);
                a0 = fma2(wv[0][j].y, xv0.y, a0);
                a1 = fma2(wv[1][j].x, xv0.x, a1);
                a1 = fma2(wv[1][j].y, xv0.y, a1);
                a2 = fma2(wv[2][j].x, xv0.x, a2);
                a2 = fma2(wv[2][j].y, xv0.y, a2);
                d0 = fma2(wv[0][j].x, xv1.x, d0);
                d0 = fma2(wv[0][j].y, xv1.y, d0);
                d1 = fma2(wv[1][j].x, xv1.x, d1);
                d1 = fma2(wv[1][j].y, xv1.y, d1);
                d2 = fma2(wv[2][j].x, xv1.x, d2);
                d2 = fma2(wv[2][j].y, xv1.y, d2);
            }
            {
                __half2 rz = __floats2half2_rn(hadd2(a0) + br, hadd2(a1) + bz);
                __half2 n0 = __floats2half2_rn(hadd2(a2) + bn, 0.f);
                uint2 pkt;
                pkt.x = *reinterpret_cast<unsigned*>(&rz);
                pkt.y = *reinterpret_cast<unsigned*>(&n0);
                *reinterpret_cast<uint2*>(outp + (size_t)k * 256) = pkt;
            }
            {
                __half2 rz = __floats2half2_rn(hadd2(d0) + br, hadd2(d1) + bz);
                __half2 n0 = __floats2half2_rn(hadd2(d2) + bn, 0.f);
                uint2 pkt;
                pkt.x = *reinterpret_cast<unsigned*>(&rz);
                pkt.y = *reinterpret_cast<unsigned*>(&n0);
                *reinterpret_cast<uint2*>(outp + (size_t)(k + 1) * 256) = pkt;
            }
        }
    }
}

// ---------------------------------------------------------------------------
// Kernel 2: forward recurrence (R13 architecture, best measured 174.7us).
// Grid 512, CTA = 64 threads = 1 row; 3.46 CTAs/SM overlap on SMSP {0,1}.
// Thread owns unit u (192 weight regs, full 64-wide dots); ONE __syncthreads
// per step; packed xg via single LDS.64. BK=32 halves boundary overhead.
// ---------------------------------------------------------------------------
__global__ __launch_bounds__(64, 4)
void gru_rec_kernel(const float* __restrict__ w_hh,
                    const float* __restrict__ b_hh,
                    const float* __restrict__ x,
                    const float* __restrict__ w_ih_b,
                    const float* __restrict__ b_ih_b,
                    const float* __restrict__ b_hh_b,
                    const float* __restrict__ fc_w,
                    const float* __restrict__ fc_b,
                    float* __restrict__ out)
{
    __shared__ __align__(16) float h_sh[2][HH];
    __shared__ __align__(16) __half xg_sh[2][BK * 256];   // 2 x 16KB
    __shared__ float red_sh[HH];

    const int u = threadIdx.x;       // unit 0..63
    const int b = blockIdx.x;

    // full rows r(u), z(u), n(u) of w_hh: 3 x 64 floats = 48 ulonglong2
    ulonglong2 w[3][16];
    {
        const int rows[3] = { u, HH + u, 2 * HH + u };
        #pragma unroll
        for (int i = 0; i < 3; i++) {
            const ulonglong2* p = (const ulonglong2*)(w_hh + rows[i] * HH);
            #pragma unroll
            for (int j = 0; j < 16; j++) w[i][j] = p[j];
        }
    }
    const float bhn = b_hh[2 * HH + u];

    const char* xg_g = (const char*)(g_xg + (size_t)b * TT * 256);
    const unsigned xg_sb = (unsigned)__cvta_generic_to_shared(&xg_sh[0][0]);
    // per block: 16384 B = 1024 x 16B chunks; 16 per thread

    float hold = 0.f;
    h_sh[0][u] = 0.f;

    // prologue: stage block 0 into buffer 0
    #pragma unroll
    for (int c = 0; c < 16; c++)
        cpa16(xg_sb + (u + 64 * c) * 16, xg_g + (u + 64 * c) * 16);
    cpa_commit();
    __syncthreads();

    int p = 0;
    for (int blk = 0; blk < NBK; ++blk) {
        if (blk + 1 < NBK) {
            unsigned dst = xg_sb + ((blk & 1) ? 0u : (unsigned)XGBB);
            const char* src = xg_g + (size_t)(blk + 1) * XGBB;
            #pragma unroll
            for (int c = 0; c < 16; c++)
                cpa16(dst + (u + 64 * c) * 16, src + (u + 64 * c) * 16);
        }
        cpa_commit();
        cpa_wait1();
        __syncthreads();

        const __half* xb = &xg_sh[blk & 1][0];

        #pragma unroll 4
        for (int tt = 0; tt < BK; ++tt) {
            // packed xg for this unit/step: one LDS.64
            uint2 pkt = *reinterpret_cast<const uint2*>(xb + tt * 256 + u * 4);
            float2 rzx = __half22float2(*reinterpret_cast<__half2*>(&pkt.x));
            float  xn  = __half2float(*reinterpret_cast<__half*>(&pkt.y));

            const ulonglong2* hp = (const ulonglong2*)&h_sh[p][0];
            ull a0 = 0ull, a1 = 0ull, a2 = 0ull;
            ull c0 = 0ull, c1 = 0ull, c2 = 0ull;
            #pragma unroll
            for (int j = 0; j < 8; j++) {
                ulonglong2 hv = hp[j];
                a0 = fma2(w[0][j].x, hv.x, a0); a0 = fma2(w[0][j].y, hv.y, a0);
                a1 = fma2(w[1][j].x, hv.x, a1); a1 = fma2(w[1][j].y, hv.y, a1);
                a2 = fma2(w[2][j].x, hv.x, a2); a2 = fma2(w[2][j].y, hv.y, a2);
            }
            #pragma unroll
            for (int j = 8; j < 16; j++) {
                ulonglong2 hv = hp[j];
                c0 = fma2(w[0][j].x, hv.x, c0); c0 = fma2(w[0][j].y, hv.y, c0);
                c1 = fma2(w[1][j].x, hv.x, c1); c1 = fma2(w[1][j].y, hv.y, c1);
                c2 = fma2(w[2][j].x, hv.x, c2); c2 = fma2(w[2][j].y, hv.y, c2);
            }

            float rr = siga(rzx.x + hadd2(addf2(a0, c0)));
            float zz = siga(rzx.y + hadd2(addf2(a1, c1)));
            float nn = tanha(fmaf(rr, hadd2(addf2(a2, c2)) + bhn, xn));
            hold = fmaf(zz, hold - nn, nn);     // (1-z)n + z h

            h_sh[p ^ 1][u] = hold;
            __syncthreads();
            p ^= 1;
        }
    }

    // ---- epilogue: backward GRU = ONE step from h=0 on x[:,T-1,:]; then fc ----
    {
        const int j = u;
        const float* xl = x + ((size_t)b * TT + (TT - 1)) * DD;
        float xv[DD];
        #pragma unroll
        for (int k = 0; k < DD; k++) xv[k] = __ldg(xl + k);

        float ar  = __ldg(b_ih_b + j)          + __ldg(b_hh_b + j);
        float az  = __ldg(b_ih_b + HH + j)     + __ldg(b_hh_b + HH + j);
        float anx = __ldg(b_ih_b + 2 * HH + j);
        float anh = __ldg(b_hh_b + 2 * HH + j);
        const float* wr = w_ih_b + (size_t)j * DD;
        const float* wz = w_ih_b + (size_t)(HH + j) * DD;
        const float* wn = w_ih_b + (size_t)(2 * HH + j) * DD;
        #pragma unroll
        for (int k = 0; k < DD; k++) {
            ar  += __ldg(wr + k) * xv[k];
            az  += __ldg(wz + k) * xv[k];
            anx += __ldg(wn + k) * xv[k];
        }
        float rb = siga(ar);
        float zb = siga(az);
        float nb = tanha(anx + rb * anh);
        float hb = (1.f - zb) * nb;            // h_prev = 0

        red_sh[j] = hold * __ldg(fc_w + j) + hb * __ldg(fc_w + HH + j);
    }
    __syncthreads();
    if (u == 0) {
        float sum = __ldg(fc_b);
        #pragma unroll
        for (int k = 0; k < HH; k++) sum += red_sh[k];
        out[b] = sum;
    }
}

extern "C" void kernel_launch(void* const* d_in, const int* in_sizes, int n_in,
                              void* d_out, int out_size)
{
    const float* x      = (const float*)d_in[0];
    const float* w_ih_f = (const float*)d_in[1];
    const float* w_hh_f = (const float*)d_in[2];
    const float* b_ih_f = (const float*)d_in[3];
    const float* b_hh_f = (const float*)d_in[4];
    const float* w_ih_b = (const float*)d_in[5];
    /* d_in[6] = w_hh_b unused: backward direction starts from h=0 */
    const float* b_ih_b = (const float*)d_in[7];
    const float* b_hh_b = (const float*)d_in[8];
    const float* fc_w   = (const float*)d_in[9];
    const float* fc_b   = (const float*)d_in[10];

    xg_kernel<<<2 * BB, 128>>>(x, w_ih_f, b_ih_f, b_hh_f);
    gru_rec_kernel<<<BB, 64>>>(w_hh_f, b_hh_f, x,
                               w_ih_b, b_ih_b, b_hh_b,
                               fc_w, fc_b, (float*)d_out);
}